// round 10
// baseline (speedup 1.0000x reference)
#include <cuda_runtime.h>
#include <cuda_bf16.h>
#include <cstdint>

// ---------------------------------------------------------------------------
// Problem constants
// ---------------------------------------------------------------------------
#define TSEQ 2048
#define NEMB 768
#define NH   12
#define HD   64
#define BATCH 2
#define MROWS (BATCH * TSEQ)   // 4096
#define QKV_W (3 * NEMB)       // 2304
#define KP    2304             // split-K' = 3 * 768

// ---------------------------------------------------------------------------
// Scratch (__device__ globals; allocation-free rule)
// ---------------------------------------------------------------------------
__device__ __align__(16) __nv_bfloat16 g_xs  [(size_t)MROWS * KP];    // [Ah|Al|Ah] of x
__device__ __align__(16) __nv_bfloat16 g_atts[(size_t)MROWS * KP];    // [Ah|Al|Ah] of att
__device__ __align__(16) __nv_bfloat16 g_wqT [(size_t)QKV_W * KP];    // [N][K'] of w_qkv
__device__ __align__(16) __nv_bfloat16 g_wpT [(size_t)NEMB  * KP];    // [N][K'] of w_proj
// pre-split Q/K/V, head-major [b*NH+h][t][64]
#define QKV_E ((size_t)BATCH * NH * TSEQ * HD)
__device__ __align__(16) __nv_bfloat16 g_qh[QKV_E];
__device__ __align__(16) __nv_bfloat16 g_ql[QKV_E];
__device__ __align__(16) __nv_bfloat16 g_kh[QKV_E];
__device__ __align__(16) __nv_bfloat16 g_kl[QKV_E];
__device__ __align__(16) __nv_bfloat16 g_vh[QKV_E];
__device__ __align__(16) __nv_bfloat16 g_vl[QKV_E];

// ---------------------------------------------------------------------------
// PTX helpers (baseline compute_103-safe: mma.sync / ldmatrix / cp.async)
// ---------------------------------------------------------------------------
__device__ __forceinline__ uint32_t smem_u32(const void* p) {
    uint32_t a;
    asm("{ .reg .u64 t; cvta.to.shared.u64 t, %1; cvt.u32.u64 %0, t; }"
        : "=r"(a) : "l"(p));
    return a;
}
__device__ __forceinline__ void ldsm_x4(uint32_t& r0, uint32_t& r1,
                                        uint32_t& r2, uint32_t& r3, uint32_t addr) {
    asm volatile("ldmatrix.sync.aligned.m8n8.x4.shared.b16 {%0,%1,%2,%3}, [%4];"
                 : "=r"(r0), "=r"(r1), "=r"(r2), "=r"(r3) : "r"(addr));
}
__device__ __forceinline__ void ldsm_x4_t(uint32_t& r0, uint32_t& r1,
                                          uint32_t& r2, uint32_t& r3, uint32_t addr) {
    asm volatile("ldmatrix.sync.aligned.m8n8.x4.trans.shared.b16 {%0,%1,%2,%3}, [%4];"
                 : "=r"(r0), "=r"(r1), "=r"(r2), "=r"(r3) : "r"(addr));
}
__device__ __forceinline__ void mma16816(float* c, const uint32_t* a, const uint32_t* b) {
    asm volatile(
        "mma.sync.aligned.m16n8k16.row.col.f32.bf16.bf16.f32 "
        "{%0,%1,%2,%3}, {%4,%5,%6,%7}, {%8,%9}, {%0,%1,%2,%3};"
        : "+f"(c[0]), "+f"(c[1]), "+f"(c[2]), "+f"(c[3])
        : "r"(a[0]), "r"(a[1]), "r"(a[2]), "r"(a[3]), "r"(b[0]), "r"(b[1]));
}
#define CP_ASYNC16(dst, src) \
    asm volatile("cp.async.cg.shared.global [%0], [%1], 16;" :: "r"(dst), "l"(src) : "memory")
#define CP_COMMIT()  asm volatile("cp.async.commit_group;" ::: "memory")
#define CP_WAIT1()   asm volatile("cp.async.wait_group 1;" ::: "memory")
#define CP_WAIT0()   asm volatile("cp.async.wait_group 0;" ::: "memory")

__device__ __forceinline__ void split2(float a, float b, uint32_t& hi, uint32_t& lo) {
    __nv_bfloat16 ha = __float2bfloat16(a), hb = __float2bfloat16(b);
    hi = (uint32_t)__bfloat16_as_ushort(ha) | ((uint32_t)__bfloat16_as_ushort(hb) << 16);
    __nv_bfloat16 la = __float2bfloat16(a - __bfloat162float(ha));
    __nv_bfloat16 lb = __float2bfloat16(b - __bfloat162float(hb));
    lo = (uint32_t)__bfloat16_as_ushort(la) | ((uint32_t)__bfloat16_as_ushort(lb) << 16);
}

// ---------------------------------------------------------------------------
// bf16 mma.sync GEMM, 3-stage single-barrier pipeline.
// MODE 0: fp32 epilogue to C. MODE 1: QKV split epilogue (Q pre-scaled 0.125).
// ---------------------------------------------------------------------------
#define BKC     64
#define ASTRIDE 72
#define TILE_E  (128 * ASTRIDE)              // 9216 bf16 per matrix tile
#define GSTAGES 3
#define GEMM_SMEM_BYTES (GSTAGES * 2 * TILE_E * 2)   // 110592
#define NCHUNK  (KP / BKC)                   // 36

template<int MODE>
__global__ __launch_bounds__(256) void gemm_bf16_mma(
    const __nv_bfloat16* __restrict__ A,
    const __nv_bfloat16* __restrict__ BT,
    float* __restrict__ C, int N,
    __nv_bfloat16* __restrict__ qh, __nv_bfloat16* __restrict__ ql,
    __nv_bfloat16* __restrict__ kh, __nv_bfloat16* __restrict__ kl,
    __nv_bfloat16* __restrict__ vh, __nv_bfloat16* __restrict__ vl)
{
    extern __shared__ __nv_bfloat16 smb[];
    const uint32_t smem_base = smem_u32(smb);

    const int tid  = threadIdx.x;
    const int wid  = tid >> 5;
    const int lane = tid & 31;
    const int wm   = wid >> 2;
    const int wn   = wid & 3;

    const int m0 = blockIdx.y * 128;
    const int n0 = blockIdx.x * 128;

    const __nv_bfloat16* Ap = A  + (size_t)m0 * KP;
    const __nv_bfloat16* Bp = BT + (size_t)n0 * KP;

    const int ldr = tid >> 3;
    const int ldc = (tid & 7) * 8;

    float acc[4][4][4];
    #pragma unroll
    for (int i = 0; i < 4; i++)
        #pragma unroll
        for (int j = 0; j < 4; j++)
            #pragma unroll
            for (int r = 0; r < 4; r++)
                acc[i][j][r] = 0.f;

    // prologue: issue chunks 0 and 1 into stages 0 and 1 (one group each)
    #pragma unroll
    for (int s = 0; s < 2; s++) {
        const uint32_t a_s = smem_base + (uint32_t)(s * 2 * TILE_E) * 2;
        const uint32_t b_s = a_s + TILE_E * 2;
        const int kc = s * BKC;
        #pragma unroll
        for (int i = 0; i < 4; i++) {
            const int r = ldr + i * 32;
            CP_ASYNC16(a_s + (uint32_t)(r * ASTRIDE + ldc) * 2,
                       Ap + (size_t)r * KP + kc + ldc);
            CP_ASYNC16(b_s + (uint32_t)(r * ASTRIDE + ldc) * 2,
                       Bp + (size_t)r * KP + kc + ldc);
        }
        CP_COMMIT();
    }

    const int a_row = wm * 64 + (lane & 15);
    const int a_col = (lane >> 4) * 8;
    const int b_row = wn * 32 + (lane & 7);
    const int b_sel = lane >> 3;
    const int b_nadd = (b_sel >> 1) * 8;
    const int b_col  = (b_sel & 1) * 8;

    int buf = 0;                 // = c % 3
    int pbuf = 2;                // = (c+2) % 3
    for (int c = 0; c < NCHUNK; c++) {
        CP_WAIT1();              // chunk c resident (newest group may be in flight)
        __syncthreads();         // all warps done with chunk c-1 (stage pbuf)

        // prefetch chunk c+2 into stage (c+2)%3; empty commit keeps group count aligned
        if (c + 2 < NCHUNK) {
            const int kc = (c + 2) * BKC;
            const uint32_t a_s = smem_base + (uint32_t)(pbuf * 2 * TILE_E) * 2;
            const uint32_t b_s = a_s + TILE_E * 2;
            #pragma unroll
            for (int i = 0; i < 4; i++) {
                const int r = ldr + i * 32;
                CP_ASYNC16(a_s + (uint32_t)(r * ASTRIDE + ldc) * 2,
                           Ap + (size_t)r * KP + kc + ldc);
                CP_ASYNC16(b_s + (uint32_t)(r * ASTRIDE + ldc) * 2,
                           Bp + (size_t)r * KP + kc + ldc);
            }
        }
        CP_COMMIT();

        const uint32_t a_base = smem_base + (uint32_t)(buf * 2 * TILE_E) * 2;
        const uint32_t b_base = a_base + TILE_E * 2;

        #pragma unroll
        for (int ks = 0; ks < 4; ks++) {
            uint32_t aF[4][4];
            uint32_t bF[4][2];
            #pragma unroll
            for (int mt = 0; mt < 4; mt++) {
                const uint32_t ad = a_base +
                    (uint32_t)((a_row + mt * 16) * ASTRIDE + ks * 16 + a_col) * 2;
                ldsm_x4(aF[mt][0], aF[mt][1], aF[mt][2], aF[mt][3], ad);
            }
            #pragma unroll
            for (int p = 0; p < 2; p++) {
                const uint32_t bd = b_base +
                    (uint32_t)((b_row + p * 16 + b_nadd) * ASTRIDE + ks * 16 + b_col) * 2;
                ldsm_x4(bF[2*p][0], bF[2*p][1], bF[2*p+1][0], bF[2*p+1][1], bd);
            }
            #pragma unroll
            for (int mt = 0; mt < 4; mt++)
                #pragma unroll
                for (int nt = 0; nt < 4; nt++)
                    mma16816(acc[mt][nt], aF[mt], bF[nt]);
        }

        buf  = (buf  == 2) ? 0 : buf + 1;
        pbuf = (pbuf == 2) ? 0 : pbuf + 1;
    }

    if (MODE == 0) {
        #pragma unroll
        for (int mt = 0; mt < 4; mt++) {
            #pragma unroll
            for (int nt = 0; nt < 4; nt++) {
                const int row = m0 + wm * 64 + mt * 16 + (lane >> 2);
                const int col = n0 + wn * 32 + nt * 8 + (lane & 3) * 2;
                float* p0 = C + (size_t)row * N + col;
                float* p1 = C + (size_t)(row + 8) * N + col;
                *reinterpret_cast<float2*>(p0) = make_float2(acc[mt][nt][0], acc[mt][nt][1]);
                *reinterpret_cast<float2*>(p1) = make_float2(acc[mt][nt][2], acc[mt][nt][3]);
            }
        }
    } else {
        #pragma unroll
        for (int mt = 0; mt < 4; mt++) {
            #pragma unroll
            for (int nt = 0; nt < 4; nt++) {
                const int col  = n0 + wn * 32 + nt * 8 + (lane & 3) * 2;
                const int sec  = col / NEMB;            // 0=q,1=k,2=v
                const int rem  = col - sec * NEMB;
                const int head = rem >> 6;
                const int d    = rem & 63;
                __nv_bfloat16* bh = (sec == 0) ? qh : (sec == 1) ? kh : vh;
                __nv_bfloat16* bl = (sec == 0) ? ql : (sec == 1) ? kl : vl;
                const float s = (sec == 0) ? 0.125f : 1.0f;
                #pragma unroll
                for (int hr = 0; hr < 2; hr++) {
                    const int row = m0 + wm * 64 + mt * 16 + (lane >> 2) + hr * 8;
                    const int bb  = row >> 11;
                    const int t   = row & 2047;
                    const size_t off = ((size_t)(bb * NH + head) * TSEQ + t) * HD + d;
                    uint32_t hi, lo;
                    split2(acc[mt][nt][hr * 2] * s, acc[mt][nt][hr * 2 + 1] * s, hi, lo);
                    *reinterpret_cast<uint32_t*>(bh + off) = hi;
                    *reinterpret_cast<uint32_t*>(bl + off) = lo;
                }
            }
        }
    }
}

// ---------------------------------------------------------------------------
// conv_split / conv_wT (unchanged)
// ---------------------------------------------------------------------------
__global__ __launch_bounds__(256) void conv_split(
    const float* __restrict__ in, __nv_bfloat16* __restrict__ out, int M)
{
    const int idx = blockIdx.x * 256 + threadIdx.x;
    if (idx >= M * NEMB) return;
    const int row = idx / NEMB;
    const int col = idx - row * NEMB;
    const float x = in[idx];
    const __nv_bfloat16 hi = __float2bfloat16(x);
    const __nv_bfloat16 lo = __float2bfloat16(x - __bfloat162float(hi));
    __nv_bfloat16* o = out + (size_t)row * KP + col;
    o[0]        = hi;
    o[NEMB]     = lo;
    o[2 * NEMB] = hi;
}

__global__ __launch_bounds__(256) void conv_wT(
    const float* __restrict__ W, __nv_bfloat16* __restrict__ WT, int N)
{
    __shared__ float t[32][33];
    const int tx = threadIdx.x & 31;
    const int ty = threadIdx.x >> 5;
    const int gn = blockIdx.x * 32;
    const int gk = blockIdx.y * 32;

    #pragma unroll
    for (int i = 0; i < 4; i++)
        t[ty + 8 * i][tx] = W[(size_t)(gk + ty + 8 * i) * N + gn + tx];
    __syncthreads();

    #pragma unroll
    for (int i = 0; i < 4; i++) {
        const int n = gn + ty + 8 * i;
        const float x = t[tx][ty + 8 * i];
        const __nv_bfloat16 hi = __float2bfloat16(x);
        const __nv_bfloat16 lo = __float2bfloat16(x - __bfloat162float(hi));
        __nv_bfloat16* o = WT + (size_t)n * KP + gk + tx;
        o[0]        = hi;
        o[NEMB]     = hi;
        o[2 * NEMB] = lo;
    }
}

// ---------------------------------------------------------------------------
// Tensor-core fused causal attention, v3 (FA-2 register passing — unchanged
// from round 7, passing at ~160us).
// ---------------------------------------------------------------------------
#define AT_QH_E  0
#define AT_QL_E  9216
#define AT_KV_E  18432                    // + buf*18432
#define AKV_SZ   4608                     // 64*72 elems
#define ATTN_SMEM_BYTES ((18432 + 2 * 18432) * 2)   // 110592

#define KV_LOAD(kt_, buf_) do {                                                   \
    const uint32_t kvs = smb + (uint32_t)(AT_KV_E + (buf_) * 18432) * 2;          \
    _Pragma("unroll")                                                             \
    for (int i_ = 0; i_ < 2; i_++) {                                              \
        const int id_ = tid + i_ * 256;                                           \
        const int r_ = id_ >> 3, c_ = (id_ & 7) * 8;                              \
        const size_t go_ = (bh + (size_t)(kt_) * 64 + r_) * HD + c_;              \
        const uint32_t so_ = (uint32_t)(r_ * 72 + c_) * 2;                        \
        CP_ASYNC16(kvs + so_,                  Kh + go_);                         \
        CP_ASYNC16(kvs + AKV_SZ * 2 + so_,     Kl + go_);                         \
        CP_ASYNC16(kvs + 2 * AKV_SZ * 2 + so_, Vh + go_);                         \
        CP_ASYNC16(kvs + 3 * AKV_SZ * 2 + so_, Vl + go_);                         \
    }                                                                             \
    CP_COMMIT();                                                                  \
} while (0)

__global__ __launch_bounds__(256, 2) void attn_mma(
    const __nv_bfloat16* __restrict__ Qh, const __nv_bfloat16* __restrict__ Ql,
    const __nv_bfloat16* __restrict__ Kh, const __nv_bfloat16* __restrict__ Kl,
    const __nv_bfloat16* __restrict__ Vh, const __nv_bfloat16* __restrict__ Vl,
    __nv_bfloat16* __restrict__ atts)
{
    extern __shared__ __nv_bfloat16 smh[];
    const uint32_t smb = smem_u32(smh);

    const int tid  = threadIdx.x;
    const int wid  = tid >> 5;           // 0..7, owns rows wid*16..+15
    const int lane = tid & 31;

    const int qt = (int)gridDim.x - 1 - (int)blockIdx.x;   // heavy tiles first
    const int h  = blockIdx.y;
    const int b  = blockIdx.z;
    const int q0 = qt * 128;

    const size_t bh = (size_t)(b * NH + h) * TSEQ;

    // ---- issue Q + KV tile 0 loads (one group) ----
    {
        const uint32_t qhs = smb + AT_QH_E * 2;
        const uint32_t qls = smb + AT_QL_E * 2;
        #pragma unroll
        for (int i = 0; i < 4; i++) {
            const int id = tid + i * 256;      // 0..1023
            const int r = id >> 3, c = (id & 7) * 8;
            const size_t go = (bh + q0 + r) * HD + c;
            const uint32_t so = (uint32_t)(r * 72 + c) * 2;
            CP_ASYNC16(qhs + so, Qh + go);
            CP_ASYNC16(qls + so, Ql + go);
        }
        KV_LOAD(0, 0);   // commits the group
    }

    // fragment addressing
    const int lr = lane >> 2;            // 0..7
    const int lc = (lane & 3) * 2;       // 0,2,4,6
    const int a_row = wid * 16 + (lane & 15);
    const int a_col = (lane >> 4) * 8;
    const int b_row = lane & 7;
    const int b_nadd = ((lane >> 4) & 1) * 8;
    const int b_col  = ((lane >> 3) & 1) * 8;
    const int v_roff = (lane & 7) + ((lane >> 3) & 1) * 8;
    const int v_coff = (lane >> 4) * 8;

    const uint32_t qh_b = smb + AT_QH_E * 2;
    const uint32_t ql_b = smb + AT_QL_E * 2;

    float oacc[8][4];
    #pragma unroll
    for (int nt = 0; nt < 8; nt++)
        #pragma unroll
        for (int r = 0; r < 4; r++)
            oacc[nt][r] = 0.f;
    float lsum0 = 0.f, lsum1 = 0.f;

    const int numT = 2 * qt + 2;
    const int wrow0 = q0 + wid * 16;     // warp's first global q-row

    CP_WAIT0();
    __syncthreads();

    for (int kt = 0; kt < numT; kt++) {
        if (kt + 1 < numT) KV_LOAD(kt + 1, (kt + 1) & 1);

        const uint32_t kvb = smb + (uint32_t)(AT_KV_E + (kt & 1) * 18432) * 2;
        const uint32_t kh_b = kvb;
        const uint32_t kl_b = kvb + AKV_SZ * 2;
        const uint32_t vh_b = kvb + 2 * AKV_SZ * 2;
        const uint32_t vl_b = kvb + 3 * AKV_SZ * 2;

        if (kt * 64 <= wrow0 + 15) {     // tile not fully masked for this warp
            // ---- Phase A: S = Q' @ K'^T ----
            float sacc[8][4];
            #pragma unroll
            for (int nt = 0; nt < 8; nt++)
                #pragma unroll
                for (int r = 0; r < 4; r++)
                    sacc[nt][r] = 0.f;

            #pragma unroll
            for (int ks = 0; ks < 4; ks++) {
                uint32_t qf[4], qg[4], bF[8][2];
                ldsm_x4(qf[0], qf[1], qf[2], qf[3],
                        qh_b + (uint32_t)(a_row * 72 + ks * 16 + a_col) * 2);
                ldsm_x4(qg[0], qg[1], qg[2], qg[3],
                        ql_b + (uint32_t)(a_row * 72 + ks * 16 + a_col) * 2);
                #pragma unroll
                for (int p = 0; p < 4; p++)
                    ldsm_x4(bF[2*p][0], bF[2*p][1], bF[2*p+1][0], bF[2*p+1][1],
                            kh_b + (uint32_t)((p * 16 + b_nadd + b_row) * 72
                                              + ks * 16 + b_col) * 2);
                #pragma unroll
                for (int nt = 0; nt < 8; nt++) mma16816(sacc[nt], qf, bF[nt]);
                #pragma unroll
                for (int nt = 0; nt < 8; nt++) mma16816(sacc[nt], qg, bF[nt]);
            }
            #pragma unroll
            for (int ks = 0; ks < 4; ks++) {
                uint32_t qf[4], bF[8][2];
                ldsm_x4(qf[0], qf[1], qf[2], qf[3],
                        qh_b + (uint32_t)(a_row * 72 + ks * 16 + a_col) * 2);
                #pragma unroll
                for (int p = 0; p < 4; p++)
                    ldsm_x4(bF[2*p][0], bF[2*p][1], bF[2*p+1][0], bF[2*p+1][1],
                            kl_b + (uint32_t)((p * 16 + b_nadd + b_row) * 72
                                              + ks * 16 + b_col) * 2);
                #pragma unroll
                for (int nt = 0; nt < 8; nt++) mma16816(sacc[nt], qf, bF[nt]);
            }

            // ---- exp + mask + register row sums ----
            const bool need_mask = (kt * 64 + 63 > wrow0);
            #pragma unroll
            for (int nt = 0; nt < 8; nt++) {
                #pragma unroll
                for (int r = 0; r < 4; r++) {
                    float e = __expf(sacc[nt][r]);
                    if (need_mask) {
                        const int colg = kt * 64 + nt * 8 + lc + (r & 1);
                        const int rowg = wrow0 + lr + (r >> 1) * 8;
                        if (colg > rowg) e = 0.f;
                    }
                    sacc[nt][r] = e;
                    if (r < 2) lsum0 += e; else lsum1 += e;
                }
            }

            // ---- pack P A-fragments directly from S C-fragments ----
            uint32_t phF[4][4], plF[4][4];
            #pragma unroll
            for (int ks = 0; ks < 4; ks++) {
                split2(sacc[2*ks][0],   sacc[2*ks][1],   phF[ks][0], plF[ks][0]);
                split2(sacc[2*ks][2],   sacc[2*ks][3],   phF[ks][1], plF[ks][1]);
                split2(sacc[2*ks+1][0], sacc[2*ks+1][1], phF[ks][2], plF[ks][2]);
                split2(sacc[2*ks+1][2], sacc[2*ks+1][3], phF[ks][3], plF[ks][3]);
            }

            // ---- Phase B: O += Ph@Vh + Pl@Vh + Ph@Vl ----
            #pragma unroll
            for (int ks = 0; ks < 4; ks++) {
                uint32_t bF[8][2];
                #pragma unroll
                for (int p = 0; p < 4; p++)
                    ldsm_x4_t(bF[2*p][0], bF[2*p][1], bF[2*p+1][0], bF[2*p+1][1],
                              vh_b + (uint32_t)((ks * 16 + v_roff) * 72
                                                + p * 16 + v_coff) * 2);
                #pragma unroll
                for (int nt = 0; nt < 8; nt++) mma16816(oacc[nt], phF[ks], bF[nt]);
                #pragma unroll
                for (int nt = 0; nt < 8; nt++) mma16816(oacc[nt], plF[ks], bF[nt]);
            }
            #pragma unroll
            for (int ks = 0; ks < 4; ks++) {
                uint32_t bF[8][2];
                #pragma unroll
                for (int p = 0; p < 4; p++)
                    ldsm_x4_t(bF[2*p][0], bF[2*p][1], bF[2*p+1][0], bF[2*p+1][1],
                              vl_b + (uint32_t)((ks * 16 + v_roff) * 72
                                                + p * 16 + v_coff) * 2);
                #pragma unroll
                for (int nt = 0; nt < 8; nt++) mma16816(oacc[nt], phF[ks], bF[nt]);
            }
        }

        if (kt + 1 < numT) {
            CP_WAIT0();
            __syncthreads();   // tile kt+1 resident & visible; all warps done with kt
        }
    }

    // ---- final row-sum reduce (within 4-lane quad) ----
    lsum0 += __shfl_xor_sync(0xFFFFFFFFu, lsum0, 1);
    lsum0 += __shfl_xor_sync(0xFFFFFFFFu, lsum0, 2);
    lsum1 += __shfl_xor_sync(0xFFFFFFFFu, lsum1, 1);
    lsum1 += __shfl_xor_sync(0xFFFFFFFFu, lsum1, 2);
    const float inv0 = 1.f / lsum0;
    const float inv1 = 1.f / lsum1;

    // ---- normalize + split-store into atts ([Ah|Al|Ah]) ----
    const size_t row0 = (size_t)(b * TSEQ + wrow0 + lr);
    #pragma unroll
    for (int nt = 0; nt < 8; nt++) {
        const int col = h * HD + nt * 8 + lc;
        uint32_t hi, lo;
        split2(oacc[nt][0] * inv0, oacc[nt][1] * inv0, hi, lo);
        __nv_bfloat16* op = atts + row0 * KP + col;
        *reinterpret_cast<uint32_t*>(op)            = hi;
        *reinterpret_cast<uint32_t*>(op + NEMB)     = lo;
        *reinterpret_cast<uint32_t*>(op + 2 * NEMB) = hi;
        split2(oacc[nt][2] * inv1, oacc[nt][3] * inv1, hi, lo);
        op = atts + (row0 + 8) * KP + col;
        *reinterpret_cast<uint32_t*>(op)            = hi;
        *reinterpret_cast<uint32_t*>(op + NEMB)     = lo;
        *reinterpret_cast<uint32_t*>(op + 2 * NEMB) = hi;
    }
}

// ---------------------------------------------------------------------------
extern "C" void kernel_launch(void* const* d_in, const int* in_sizes, int n_in,
                              void* d_out, int out_size)
{
    const float* x      = (const float*)d_in[0];   // [2,2048,768]
    const float* w_qkv  = (const float*)d_in[1];   // [768,2304]
    const float* w_proj = (const float*)d_in[2];   // [768,768]
    float* out = (float*)d_out;                    // [2,2048,768]

    __nv_bfloat16 *xs, *atts, *wqT, *wpT, *qh, *ql, *kh, *kl, *vh, *vl;
    cudaGetSymbolAddress((void**)&xs,   g_xs);
    cudaGetSymbolAddress((void**)&atts, g_atts);
    cudaGetSymbolAddress((void**)&wqT,  g_wqT);
    cudaGetSymbolAddress((void**)&wpT,  g_wpT);
    cudaGetSymbolAddress((void**)&qh,   g_qh);
    cudaGetSymbolAddress((void**)&ql,   g_ql);
    cudaGetSymbolAddress((void**)&kh,   g_kh);
    cudaGetSymbolAddress((void**)&kl,   g_kl);
    cudaGetSymbolAddress((void**)&vh,   g_vh);
    cudaGetSymbolAddress((void**)&vl,   g_vl);

    cudaFuncSetAttribute(gemm_bf16_mma<0>,
                         cudaFuncAttributeMaxDynamicSharedMemorySize, GEMM_SMEM_BYTES);
    cudaFuncSetAttribute(gemm_bf16_mma<1>,
                         cudaFuncAttributeMaxDynamicSharedMemorySize, GEMM_SMEM_BYTES);
    cudaFuncSetAttribute(attn_mma,
                         cudaFuncAttributeMaxDynamicSharedMemorySize, ATTN_SMEM_BYTES);

    // 0) split/convert inputs
    conv_split<<<(MROWS * NEMB + 255) / 256, 256>>>(x, xs, MROWS);
    conv_wT<<<dim3(QKV_W / 32, NEMB / 32), 256>>>(w_qkv, wqT, QKV_W);
    conv_wT<<<dim3(NEMB / 32, NEMB / 32), 256>>>(w_proj, wpT, NEMB);

    // 1) qkv GEMM with split epilogue -> pre-split Q/K/V buffers
    gemm_bf16_mma<1><<<dim3(QKV_W / 128, MROWS / 128), 256, GEMM_SMEM_BYTES>>>(
        xs, wqT, nullptr, QKV_W, qh, ql, kh, kl, vh, vl);

    // 2) fused causal attention -> atts (pre-split for proj)
    attn_mma<<<dim3(TSEQ / 128, NH, BATCH), 256, ATTN_SMEM_BYTES>>>(
        qh, ql, kh, kl, vh, vl, atts);

    // 3) out = att @ w_proj
    gemm_bf16_mma<0><<<dim3(NEMB / 128, MROWS / 128), 256, GEMM_SMEM_BYTES>>>(
        atts, wpT, out, NEMB, nullptr, nullptr, nullptr, nullptr, nullptr, nullptr);
}

// round 12
// speedup vs baseline: 1.0170x; 1.0170x over previous
#include <cuda_runtime.h>
#include <cuda_bf16.h>
#include <cstdint>

// ---------------------------------------------------------------------------
// Problem constants
// ---------------------------------------------------------------------------
#define TSEQ 2048
#define NEMB 768
#define NH   12
#define HD   64
#define BATCH 2
#define MROWS (BATCH * TSEQ)   // 4096
#define QKV_W (3 * NEMB)       // 2304
#define KP    2304             // split-K' = 3 * 768

// ---------------------------------------------------------------------------
// Scratch (__device__ globals; allocation-free rule)
// ---------------------------------------------------------------------------
__device__ __align__(16) __nv_bfloat16 g_xs  [(size_t)MROWS * KP];    // [Ah|Al|Ah] of x
__device__ __align__(16) __nv_bfloat16 g_atts[(size_t)MROWS * KP];    // [Ah|Al|Ah] of att
__device__ __align__(16) __nv_bfloat16 g_wqT [(size_t)QKV_W * KP];    // [N][K'] of w_qkv
__device__ __align__(16) __nv_bfloat16 g_wpT [(size_t)NEMB  * KP];    // [N][K'] of w_proj
// pre-split Q/K/V, head-major [b*NH+h][t][64]
#define QKV_E ((size_t)BATCH * NH * TSEQ * HD)
__device__ __align__(16) __nv_bfloat16 g_qh[QKV_E];
__device__ __align__(16) __nv_bfloat16 g_ql[QKV_E];
__device__ __align__(16) __nv_bfloat16 g_kh[QKV_E];
__device__ __align__(16) __nv_bfloat16 g_kl[QKV_E];
__device__ __align__(16) __nv_bfloat16 g_vh[QKV_E];
__device__ __align__(16) __nv_bfloat16 g_vl[QKV_E];

// ---------------------------------------------------------------------------
// PTX helpers
// ---------------------------------------------------------------------------
__device__ __forceinline__ uint32_t smem_u32(const void* p) {
    uint32_t a;
    asm("{ .reg .u64 t; cvta.to.shared.u64 t, %1; cvt.u32.u64 %0, t; }"
        : "=r"(a) : "l"(p));
    return a;
}
__device__ __forceinline__ void ldsm_x4(uint32_t& r0, uint32_t& r1,
                                        uint32_t& r2, uint32_t& r3, uint32_t addr) {
    asm volatile("ldmatrix.sync.aligned.m8n8.x4.shared.b16 {%0,%1,%2,%3}, [%4];"
                 : "=r"(r0), "=r"(r1), "=r"(r2), "=r"(r3) : "r"(addr));
}
__device__ __forceinline__ void ldsm_x4_t(uint32_t& r0, uint32_t& r1,
                                          uint32_t& r2, uint32_t& r3, uint32_t addr) {
    asm volatile("ldmatrix.sync.aligned.m8n8.x4.trans.shared.b16 {%0,%1,%2,%3}, [%4];"
                 : "=r"(r0), "=r"(r1), "=r"(r2), "=r"(r3) : "r"(addr));
}
__device__ __forceinline__ void mma16816(float* c, const uint32_t* a, const uint32_t* b) {
    asm volatile(
        "mma.sync.aligned.m16n8k16.row.col.f32.bf16.bf16.f32 "
        "{%0,%1,%2,%3}, {%4,%5,%6,%7}, {%8,%9}, {%0,%1,%2,%3};"
        : "+f"(c[0]), "+f"(c[1]), "+f"(c[2]), "+f"(c[3])
        : "r"(a[0]), "r"(a[1]), "r"(a[2]), "r"(a[3]), "r"(b[0]), "r"(b[1]));
}
#define CP_ASYNC16(dst, src) \
    asm volatile("cp.async.cg.shared.global [%0], [%1], 16;" :: "r"(dst), "l"(src) : "memory")
#define CP_COMMIT()  asm volatile("cp.async.commit_group;" ::: "memory")
#define CP_WAIT1()   asm volatile("cp.async.wait_group 1;" ::: "memory")
#define CP_WAIT0()   asm volatile("cp.async.wait_group 0;" ::: "memory")

__device__ __forceinline__ void split2(float a, float b, uint32_t& hi, uint32_t& lo) {
    __nv_bfloat16 ha = __float2bfloat16(a), hb = __float2bfloat16(b);
    hi = (uint32_t)__bfloat16_as_ushort(ha) | ((uint32_t)__bfloat16_as_ushort(hb) << 16);
    __nv_bfloat16 la = __float2bfloat16(a - __bfloat162float(ha));
    __nv_bfloat16 lb = __float2bfloat16(b - __bfloat162float(hb));
    lo = (uint32_t)__bfloat16_as_ushort(la) | ((uint32_t)__bfloat16_as_ushort(lb) << 16);
}

#define BKC     64
#define ASTRIDE 72
#define NCHUNK  (KP / BKC)                   // 36

// ---------------------------------------------------------------------------
// WIDE bf16 GEMM for QKV: block 128(M)x256(N), 8 warps @ 64x64, 2-stage.
// Epilogue: QKV split -> g_qh/ql/kh/kl/vh/vl (Q pre-scaled by 0.125).
// ---------------------------------------------------------------------------
#define WTILE_A_E (128 * ASTRIDE)            // 9216
#define WTILE_B_E (256 * ASTRIDE)            // 18432
#define WSTAGE_E  (WTILE_A_E + WTILE_B_E)    // 27648
#define GEMMW_SMEM_BYTES (2 * WSTAGE_E * 2)  // 110592

__global__ __launch_bounds__(256) void gemm_wide_qkv(
    const __nv_bfloat16* __restrict__ A,
    const __nv_bfloat16* __restrict__ BT,
    __nv_bfloat16* __restrict__ qh, __nv_bfloat16* __restrict__ ql,
    __nv_bfloat16* __restrict__ kh, __nv_bfloat16* __restrict__ kl,
    __nv_bfloat16* __restrict__ vh, __nv_bfloat16* __restrict__ vl)
{
    extern __shared__ __nv_bfloat16 smb[];
    const uint32_t smem_base = smem_u32(smb);

    const int tid  = threadIdx.x;
    const int wid  = tid >> 5;
    const int lane = tid & 31;
    const int wm   = wid >> 2;          // 0..1 : 64 M-rows
    const int wn   = wid & 3;           // 0..3 : 64 N-cols

    const int m0 = blockIdx.y * 128;
    const int n0 = blockIdx.x * 256;

    const __nv_bfloat16* Ap = A  + (size_t)m0 * KP;
    const __nv_bfloat16* Bp = BT + (size_t)n0 * KP;

    const int ldr = tid >> 3;           // 0..31
    const int ldc = (tid & 7) * 8;

    float acc[4][8][4];
    #pragma unroll
    for (int i = 0; i < 4; i++)
        #pragma unroll
        for (int j = 0; j < 8; j++)
            #pragma unroll
            for (int r = 0; r < 4; r++)
                acc[i][j][r] = 0.f;

    // issue chunk 0 into stage 0
    {
        const uint32_t a_s = smem_base;
        const uint32_t b_s = smem_base + WTILE_A_E * 2;
        #pragma unroll
        for (int i = 0; i < 4; i++) {
            const int r = ldr + i * 32;
            CP_ASYNC16(a_s + (uint32_t)(r * ASTRIDE + ldc) * 2,
                       Ap + (size_t)r * KP + ldc);
        }
        #pragma unroll
        for (int i = 0; i < 8; i++) {
            const int r = ldr + i * 32;
            CP_ASYNC16(b_s + (uint32_t)(r * ASTRIDE + ldc) * 2,
                       Bp + (size_t)r * KP + ldc);
        }
        CP_COMMIT();
    }

    // fragment addressing
    const int a_row = wm * 64 + (lane & 15);
    const int a_col = (lane >> 4) * 8;
    const int b_row = lane & 7;                    // 64-row B pattern (as in attn)
    const int b_nadd = ((lane >> 4) & 1) * 8;
    const int b_col  = ((lane >> 3) & 1) * 8;

    for (int c = 0; c < NCHUNK; c++) {
        if (c + 1 < NCHUNK) {
            const int nb = (c + 1) & 1;
            const int kc = (c + 1) * BKC;
            const uint32_t a_s = smem_base + (uint32_t)(nb * WSTAGE_E) * 2;
            const uint32_t b_s = a_s + WTILE_A_E * 2;
            #pragma unroll
            for (int i = 0; i < 4; i++) {
                const int r = ldr + i * 32;
                CP_ASYNC16(a_s + (uint32_t)(r * ASTRIDE + ldc) * 2,
                           Ap + (size_t)r * KP + kc + ldc);
            }
            #pragma unroll
            for (int i = 0; i < 8; i++) {
                const int r = ldr + i * 32;
                CP_ASYNC16(b_s + (uint32_t)(r * ASTRIDE + ldc) * 2,
                           Bp + (size_t)r * KP + kc + ldc);
            }
        }
        CP_COMMIT();
        CP_WAIT1();
        __syncthreads();

        const int cb = c & 1;
        const uint32_t a_base = smem_base + (uint32_t)(cb * WSTAGE_E) * 2;
        const uint32_t b_base = a_base + WTILE_A_E * 2;

        #pragma unroll
        for (int ks = 0; ks < 4; ks++) {
            uint32_t aF[4][4];
            uint32_t bF[8][2];
            #pragma unroll
            for (int mt = 0; mt < 4; mt++)
                ldsm_x4(aF[mt][0], aF[mt][1], aF[mt][2], aF[mt][3],
                        a_base + (uint32_t)((a_row + mt * 16) * ASTRIDE
                                            + ks * 16 + a_col) * 2);
            #pragma unroll
            for (int p = 0; p < 4; p++)
                ldsm_x4(bF[2*p][0], bF[2*p][1], bF[2*p+1][0], bF[2*p+1][1],
                        b_base + (uint32_t)((wn * 64 + p * 16 + b_nadd + b_row) * ASTRIDE
                                            + ks * 16 + b_col) * 2);
            #pragma unroll
            for (int mt = 0; mt < 4; mt++)
                #pragma unroll
                for (int nt = 0; nt < 8; nt++)
                    mma16816(acc[mt][nt], aF[mt], bF[nt]);
        }
        __syncthreads();
    }

    // QKV split epilogue
    #pragma unroll
    for (int mt = 0; mt < 4; mt++) {
        #pragma unroll
        for (int nt = 0; nt < 8; nt++) {
            const int col  = n0 + wn * 64 + nt * 8 + (lane & 3) * 2;
            const int sec  = col / NEMB;            // 0=q,1=k,2=v
            const int rem  = col - sec * NEMB;
            const int head = rem >> 6;
            const int d    = rem & 63;
            __nv_bfloat16* bh = (sec == 0) ? qh : (sec == 1) ? kh : vh;
            __nv_bfloat16* bl = (sec == 0) ? ql : (sec == 1) ? kl : vl;
            const float s = (sec == 0) ? 0.125f : 1.0f;
            #pragma unroll
            for (int hr = 0; hr < 2; hr++) {
                const int row = m0 + wm * 64 + mt * 16 + (lane >> 2) + hr * 8;
                const int bb  = row >> 11;
                const int t   = row & 2047;
                const size_t off = ((size_t)(bb * NH + head) * TSEQ + t) * HD + d;
                uint32_t hi, lo;
                split2(acc[mt][nt][hr * 2] * s, acc[mt][nt][hr * 2 + 1] * s, hi, lo);
                *reinterpret_cast<uint32_t*>(bh + off) = hi;
                *reinterpret_cast<uint32_t*>(bl + off) = lo;
            }
        }
    }
}

// ---------------------------------------------------------------------------
// NARROW bf16 GEMM (round-7 proven): block 128x128, warp 64x32, 2-stage.
// fp32 epilogue (used for proj).
// ---------------------------------------------------------------------------
#define TILE_E  (128 * ASTRIDE)
#define GEMM_SMEM_BYTES (4 * TILE_E * 2)     // 73728

__global__ __launch_bounds__(256) void gemm_narrow(
    const __nv_bfloat16* __restrict__ A,
    const __nv_bfloat16* __restrict__ BT,
    float* __restrict__ C, int N)
{
    extern __shared__ __nv_bfloat16 smb[];
    const uint32_t smem_base = smem_u32(smb);

    const int tid  = threadIdx.x;
    const int wid  = tid >> 5;
    const int lane = tid & 31;
    const int wm   = wid >> 2;
    const int wn   = wid & 3;

    const int m0 = blockIdx.y * 128;
    const int n0 = blockIdx.x * 128;

    const __nv_bfloat16* Ap = A  + (size_t)m0 * KP;
    const __nv_bfloat16* Bp = BT + (size_t)n0 * KP;

    const int ldr = tid >> 3;
    const int ldc = (tid & 7) * 8;

    float acc[4][4][4];
    #pragma unroll
    for (int i = 0; i < 4; i++)
        #pragma unroll
        for (int j = 0; j < 4; j++)
            #pragma unroll
            for (int r = 0; r < 4; r++)
                acc[i][j][r] = 0.f;

    {
        const uint32_t a_s = smem_base;
        const uint32_t b_s = smem_base + TILE_E * 2;
        #pragma unroll
        for (int i = 0; i < 4; i++) {
            const int r = ldr + i * 32;
            CP_ASYNC16(a_s + (uint32_t)(r * ASTRIDE + ldc) * 2,
                       Ap + (size_t)r * KP + ldc);
            CP_ASYNC16(b_s + (uint32_t)(r * ASTRIDE + ldc) * 2,
                       Bp + (size_t)r * KP + ldc);
        }
        CP_COMMIT();
    }

    const int a_row = wm * 64 + (lane & 15);
    const int a_col = (lane >> 4) * 8;
    const int b_row = wn * 32 + (lane & 7);
    const int b_sel = lane >> 3;
    const int b_nadd = (b_sel >> 1) * 8;
    const int b_col  = (b_sel & 1) * 8;

    for (int c = 0; c < NCHUNK; c++) {
        if (c + 1 < NCHUNK) {
            const int nb = (c + 1) & 1;
            const int kc = (c + 1) * BKC;
            const uint32_t a_s = smem_base + (uint32_t)(nb * 2 * TILE_E) * 2;
            const uint32_t b_s = smem_base + (uint32_t)((nb * 2 + 1) * TILE_E) * 2;
            #pragma unroll
            for (int i = 0; i < 4; i++) {
                const int r = ldr + i * 32;
                CP_ASYNC16(a_s + (uint32_t)(r * ASTRIDE + ldc) * 2,
                           Ap + (size_t)r * KP + kc + ldc);
                CP_ASYNC16(b_s + (uint32_t)(r * ASTRIDE + ldc) * 2,
                           Bp + (size_t)r * KP + kc + ldc);
            }
        }
        CP_COMMIT();
        CP_WAIT1();
        __syncthreads();

        const int cb = c & 1;
        const uint32_t a_base = smem_base + (uint32_t)(cb * 2 * TILE_E) * 2;
        const uint32_t b_base = smem_base + (uint32_t)((cb * 2 + 1) * TILE_E) * 2;

        #pragma unroll
        for (int ks = 0; ks < 4; ks++) {
            uint32_t aF[4][4];
            uint32_t bF[4][2];
            #pragma unroll
            for (int mt = 0; mt < 4; mt++)
                ldsm_x4(aF[mt][0], aF[mt][1], aF[mt][2], aF[mt][3],
                        a_base + (uint32_t)((a_row + mt * 16) * ASTRIDE
                                            + ks * 16 + a_col) * 2);
            #pragma unroll
            for (int p = 0; p < 2; p++)
                ldsm_x4(bF[2*p][0], bF[2*p][1], bF[2*p+1][0], bF[2*p+1][1],
                        b_base + (uint32_t)((b_row + p * 16 + b_nadd) * ASTRIDE
                                            + ks * 16 + b_col) * 2);
            #pragma unroll
            for (int mt = 0; mt < 4; mt++)
                #pragma unroll
                for (int nt = 0; nt < 4; nt++)
                    mma16816(acc[mt][nt], aF[mt], bF[nt]);
        }
        __syncthreads();
    }

    #pragma unroll
    for (int mt = 0; mt < 4; mt++) {
        #pragma unroll
        for (int nt = 0; nt < 4; nt++) {
            const int row = m0 + wm * 64 + mt * 16 + (lane >> 2);
            const int col = n0 + wn * 32 + nt * 8 + (lane & 3) * 2;
            float* p0 = C + (size_t)row * N + col;
            float* p1 = C + (size_t)(row + 8) * N + col;
            *reinterpret_cast<float2*>(p0) = make_float2(acc[mt][nt][0], acc[mt][nt][1]);
            *reinterpret_cast<float2*>(p1) = make_float2(acc[mt][nt][2], acc[mt][nt][3]);
        }
    }
}

// ---------------------------------------------------------------------------
// conv_split / conv_wT (unchanged)
// ---------------------------------------------------------------------------
__global__ __launch_bounds__(256) void conv_split(
    const float* __restrict__ in, __nv_bfloat16* __restrict__ out, int M)
{
    const int idx = blockIdx.x * 256 + threadIdx.x;
    if (idx >= M * NEMB) return;
    const int row = idx / NEMB;
    const int col = idx - row * NEMB;
    const float x = in[idx];
    const __nv_bfloat16 hi = __float2bfloat16(x);
    const __nv_bfloat16 lo = __float2bfloat16(x - __bfloat162float(hi));
    __nv_bfloat16* o = out + (size_t)row * KP + col;
    o[0]        = hi;
    o[NEMB]     = lo;
    o[2 * NEMB] = hi;
}

__global__ __launch_bounds__(256) void conv_wT(
    const float* __restrict__ W, __nv_bfloat16* __restrict__ WT, int N)
{
    __shared__ float t[32][33];
    const int tx = threadIdx.x & 31;
    const int ty = threadIdx.x >> 5;
    const int gn = blockIdx.x * 32;
    const int gk = blockIdx.y * 32;

    #pragma unroll
    for (int i = 0; i < 4; i++)
        t[ty + 8 * i][tx] = W[(size_t)(gk + ty + 8 * i) * N + gn + tx];
    __syncthreads();

    #pragma unroll
    for (int i = 0; i < 4; i++) {
        const int n = gn + ty + 8 * i;
        const float x = t[tx][ty + 8 * i];
        const __nv_bfloat16 hi = __float2bfloat16(x);
        const __nv_bfloat16 lo = __float2bfloat16(x - __bfloat162float(hi));
        __nv_bfloat16* o = WT + (size_t)n * KP + gk + tx;
        o[0]        = hi;
        o[NEMB]     = hi;
        o[2 * NEMB] = lo;
    }
}

// ---------------------------------------------------------------------------
// Tensor-core fused causal attention (round-7, unchanged — ~160us)
// ---------------------------------------------------------------------------
#define AT_QH_E  0
#define AT_QL_E  9216
#define AT_KV_E  18432                    // + buf*18432
#define AKV_SZ   4608                     // 64*72 elems
#define ATTN_SMEM_BYTES ((18432 + 2 * 18432) * 2)   // 110592

#define KV_LOAD(kt_, buf_) do {                                                   \
    const uint32_t kvs = smb + (uint32_t)(AT_KV_E + (buf_) * 18432) * 2;          \
    _Pragma("unroll")                                                             \
    for (int i_ = 0; i_ < 2; i_++) {                                              \
        const int id_ = tid + i_ * 256;                                           \
        const int r_ = id_ >> 3, c_ = (id_ & 7) * 8;                              \
        const size_t go_ = (bh + (size_t)(kt_) * 64 + r_) * HD + c_;              \
        const uint32_t so_ = (uint32_t)(r_ * 72 + c_) * 2;                        \
        CP_ASYNC16(kvs + so_,                  Kh + go_);                         \
        CP_ASYNC16(kvs + AKV_SZ * 2 + so_,     Kl + go_);                         \
        CP_ASYNC16(kvs + 2 * AKV_SZ * 2 + so_, Vh + go_);                         \
        CP_ASYNC16(kvs + 3 * AKV_SZ * 2 + so_, Vl + go_);                         \
    }                                                                             \
    CP_COMMIT();                                                                  \
} while (0)

__global__ __launch_bounds__(256, 2) void attn_mma(
    const __nv_bfloat16* __restrict__ Qh, const __nv_bfloat16* __restrict__ Ql,
    const __nv_bfloat16* __restrict__ Kh, const __nv_bfloat16* __restrict__ Kl,
    const __nv_bfloat16* __restrict__ Vh, const __nv_bfloat16* __restrict__ Vl,
    __nv_bfloat16* __restrict__ atts)
{
    extern __shared__ __nv_bfloat16 smh[];
    const uint32_t smb = smem_u32(smh);

    const int tid  = threadIdx.x;
    const int wid  = tid >> 5;           // 0..7, owns rows wid*16..+15
    const int lane = tid & 31;

    const int qt = (int)gridDim.x - 1 - (int)blockIdx.x;   // heavy tiles first
    const int h  = blockIdx.y;
    const int b  = blockIdx.z;
    const int q0 = qt * 128;

    const size_t bh = (size_t)(b * NH + h) * TSEQ;

    // ---- issue Q + KV tile 0 loads (one group) ----
    {
        const uint32_t qhs = smb + AT_QH_E * 2;
        const uint32_t qls = smb + AT_QL_E * 2;
        #pragma unroll
        for (int i = 0; i < 4; i++) {
            const int id = tid + i * 256;      // 0..1023
            const int r = id >> 3, c = (id & 7) * 8;
            const size_t go = (bh + q0 + r) * HD + c;
            const uint32_t so = (uint32_t)(r * 72 + c) * 2;
            CP_ASYNC16(qhs + so, Qh + go);
            CP_ASYNC16(qls + so, Ql + go);
        }
        KV_LOAD(0, 0);   // commits the group
    }

    // fragment addressing
    const int lr = lane >> 2;            // 0..7
    const int lc = (lane & 3) * 2;       // 0,2,4,6
    const int a_row = wid * 16 + (lane & 15);
    const int a_col = (lane >> 4) * 8;
    const int b_row = lane & 7;
    const int b_nadd = ((lane >> 4) & 1) * 8;
    const int b_col  = ((lane >> 3) & 1) * 8;
    const int v_roff = (lane & 7) + ((lane >> 3) & 1) * 8;
    const int v_coff = (lane >> 4) * 8;

    const uint32_t qh_b = smb + AT_QH_E * 2;
    const uint32_t ql_b = smb + AT_QL_E * 2;

    float oacc[8][4];
    #pragma unroll
    for (int nt = 0; nt < 8; nt++)
        #pragma unroll
        for (int r = 0; r < 4; r++)
            oacc[nt][r] = 0.f;
    float lsum0 = 0.f, lsum1 = 0.f;

    const int numT = 2 * qt + 2;
    const int wrow0 = q0 + wid * 16;     // warp's first global q-row

    CP_WAIT0();
    __syncthreads();

    for (int kt = 0; kt < numT; kt++) {
        if (kt + 1 < numT) KV_LOAD(kt + 1, (kt + 1) & 1);

        const uint32_t kvb = smb + (uint32_t)(AT_KV_E + (kt & 1) * 18432) * 2;
        const uint32_t kh_b = kvb;
        const uint32_t kl_b = kvb + AKV_SZ * 2;
        const uint32_t vh_b = kvb + 2 * AKV_SZ * 2;
        const uint32_t vl_b = kvb + 3 * AKV_SZ * 2;

        if (kt * 64 <= wrow0 + 15) {     // tile not fully masked for this warp
            // ---- Phase A: S = Q' @ K'^T ----
            float sacc[8][4];
            #pragma unroll
            for (int nt = 0; nt < 8; nt++)
                #pragma unroll
                for (int r = 0; r < 4; r++)
                    sacc[nt][r] = 0.f;

            #pragma unroll
            for (int ks = 0; ks < 4; ks++) {
                uint32_t qf[4], qg[4], bF[8][2];
                ldsm_x4(qf[0], qf[1], qf[2], qf[3],
                        qh_b + (uint32_t)(a_row * 72 + ks * 16 + a_col) * 2);
                ldsm_x4(qg[0], qg[1], qg[2], qg[3],
                        ql_b + (uint32_t)(a_row * 72 + ks * 16 + a_col) * 2);
                #pragma unroll
                for (int p = 0; p < 4; p++)
                    ldsm_x4(bF[2*p][0], bF[2*p][1], bF[2*p+1][0], bF[2*p+1][1],
                            kh_b + (uint32_t)((p * 16 + b_nadd + b_row) * 72
                                              + ks * 16 + b_col) * 2);
                #pragma unroll
                for (int nt = 0; nt < 8; nt++) mma16816(sacc[nt], qf, bF[nt]);
                #pragma unroll
                for (int nt = 0; nt < 8; nt++) mma16816(sacc[nt], qg, bF[nt]);
            }
            #pragma unroll
            for (int ks = 0; ks < 4; ks++) {
                uint32_t qf[4], bF[8][2];
                ldsm_x4(qf[0], qf[1], qf[2], qf[3],
                        qh_b + (uint32_t)(a_row * 72 + ks * 16 + a_col) * 2);
                #pragma unroll
                for (int p = 0; p < 4; p++)
                    ldsm_x4(bF[2*p][0], bF[2*p][1], bF[2*p+1][0], bF[2*p+1][1],
                            kl_b + (uint32_t)((p * 16 + b_nadd + b_row) * 72
                                              + ks * 16 + b_col) * 2);
                #pragma unroll
                for (int nt = 0; nt < 8; nt++) mma16816(sacc[nt], qf, bF[nt]);
            }

            // ---- exp + mask + register row sums ----
            const bool need_mask = (kt * 64 + 63 > wrow0);
            #pragma unroll
            for (int nt = 0; nt < 8; nt++) {
                #pragma unroll
                for (int r = 0; r < 4; r++) {
                    float e = __expf(sacc[nt][r]);
                    if (need_mask) {
                        const int colg = kt * 64 + nt * 8 + lc + (r & 1);
                        const int rowg = wrow0 + lr + (r >> 1) * 8;
                        if (colg > rowg) e = 0.f;
                    }
                    sacc[nt][r] = e;
                    if (r < 2) lsum0 += e; else lsum1 += e;
                }
            }

            // ---- pack P A-fragments directly from S C-fragments ----
            uint32_t phF[4][4], plF[4][4];
            #pragma unroll
            for (int ks = 0; ks < 4; ks++) {
                split2(sacc[2*ks][0],   sacc[2*ks][1],   phF[ks][0], plF[ks][0]);
                split2(sacc[2*ks][2],   sacc[2*ks][3],   phF[ks][1], plF[ks][1]);
                split2(sacc[2*ks+1][0], sacc[2*ks+1][1], phF[ks][2], plF[ks][2]);
                split2(sacc[2*ks+1][2], sacc[2*ks+1][3], phF[ks][3], plF[ks][3]);
            }

            // ---- Phase B: O += Ph@Vh + Pl@Vh + Ph@Vl ----
            #pragma unroll
            for (int ks = 0; ks < 4; ks++) {
                uint32_t bF[8][2];
                #pragma unroll
                for (int p = 0; p < 4; p++)
                    ldsm_x4_t(bF[2*p][0], bF[2*p][1], bF[2*p+1][0], bF[2*p+1][1],
                              vh_b + (uint32_t)((ks * 16 + v_roff) * 72
                                                + p * 16 + v_coff) * 2);
                #pragma unroll
                for (int nt = 0; nt < 8; nt++) mma16816(oacc[nt], phF[ks], bF[nt]);
                #pragma unroll
                for (int nt = 0; nt < 8; nt++) mma16816(oacc[nt], plF[ks], bF[nt]);
            }
            #pragma unroll
            for (int ks = 0; ks < 4; ks++) {
                uint32_t bF[8][2];
                #pragma unroll
                for (int p = 0; p < 4; p++)
                    ldsm_x4_t(bF[2*p][0], bF[2*p][1], bF[2*p+1][0], bF[2*p+1][1],
                              vl_b + (uint32_t)((ks * 16 + v_roff) * 72
                                                + p * 16 + v_coff) * 2);
                #pragma unroll
                for (int nt = 0; nt < 8; nt++) mma16816(oacc[nt], phF[ks], bF[nt]);
            }
        }

        if (kt + 1 < numT) {
            CP_WAIT0();
            __syncthreads();   // tile kt+1 resident & visible; all warps done with kt
        }
    }

    // ---- final row-sum reduce (within 4-lane quad) ----
    lsum0 += __shfl_xor_sync(0xFFFFFFFFu, lsum0, 1);
    lsum0 += __shfl_xor_sync(0xFFFFFFFFu, lsum0, 2);
    lsum1 += __shfl_xor_sync(0xFFFFFFFFu, lsum1, 1);
    lsum1 += __shfl_xor_sync(0xFFFFFFFFu, lsum1, 2);
    const float inv0 = 1.f / lsum0;
    const float inv1 = 1.f / lsum1;

    // ---- normalize + split-store into atts ([Ah|Al|Ah]) ----
    const size_t row0 = (size_t)(b * TSEQ + wrow0 + lr);
    #pragma unroll
    for (int nt = 0; nt < 8; nt++) {
        const int col = h * HD + nt * 8 + lc;
        uint32_t hi, lo;
        split2(oacc[nt][0] * inv0, oacc[nt][1] * inv0, hi, lo);
        __nv_bfloat16* op = atts + row0 * KP + col;
        *reinterpret_cast<uint32_t*>(op)            = hi;
        *reinterpret_cast<uint32_t*>(op + NEMB)     = lo;
        *reinterpret_cast<uint32_t*>(op + 2 * NEMB) = hi;
        split2(oacc[nt][2] * inv1, oacc[nt][3] * inv1, hi, lo);
        op = atts + (row0 + 8) * KP + col;
        *reinterpret_cast<uint32_t*>(op)            = hi;
        *reinterpret_cast<uint32_t*>(op + NEMB)     = lo;
        *reinterpret_cast<uint32_t*>(op + 2 * NEMB) = hi;
    }
}

// ---------------------------------------------------------------------------
extern "C" void kernel_launch(void* const* d_in, const int* in_sizes, int n_in,
                              void* d_out, int out_size)
{
    const float* x      = (const float*)d_in[0];   // [2,2048,768]
    const float* w_qkv  = (const float*)d_in[1];   // [768,2304]
    const float* w_proj = (const float*)d_in[2];   // [768,768]
    float* out = (float*)d_out;                    // [2,2048,768]

    __nv_bfloat16 *xs, *atts, *wqT, *wpT, *qh, *ql, *kh, *kl, *vh, *vl;
    cudaGetSymbolAddress((void**)&xs,   g_xs);
    cudaGetSymbolAddress((void**)&atts, g_atts);
    cudaGetSymbolAddress((void**)&wqT,  g_wqT);
    cudaGetSymbolAddress((void**)&wpT,  g_wpT);
    cudaGetSymbolAddress((void**)&qh,   g_qh);
    cudaGetSymbolAddress((void**)&ql,   g_ql);
    cudaGetSymbolAddress((void**)&kh,   g_kh);
    cudaGetSymbolAddress((void**)&kl,   g_kl);
    cudaGetSymbolAddress((void**)&vh,   g_vh);
    cudaGetSymbolAddress((void**)&vl,   g_vl);

    cudaFuncSetAttribute(gemm_wide_qkv,
                         cudaFuncAttributeMaxDynamicSharedMemorySize, GEMMW_SMEM_BYTES);
    cudaFuncSetAttribute(gemm_narrow,
                         cudaFuncAttributeMaxDynamicSharedMemorySize, GEMM_SMEM_BYTES);
    cudaFuncSetAttribute(attn_mma,
                         cudaFuncAttributeMaxDynamicSharedMemorySize, ATTN_SMEM_BYTES);

    // 0) split/convert inputs
    conv_split<<<(MROWS * NEMB + 255) / 256, 256>>>(x, xs, MROWS);
    conv_wT<<<dim3(QKV_W / 32, NEMB / 32), 256>>>(w_qkv, wqT, QKV_W);
    conv_wT<<<dim3(NEMB / 32, NEMB / 32), 256>>>(w_proj, wpT, NEMB);

    // 1) qkv GEMM (wide tiles) with split epilogue -> pre-split Q/K/V
    gemm_wide_qkv<<<dim3(QKV_W / 256, MROWS / 128), 256, GEMMW_SMEM_BYTES>>>(
        xs, wqT, qh, ql, kh, kl, vh, vl);

    // 2) fused causal attention -> atts (pre-split for proj)
    attn_mma<<<dim3(TSEQ / 128, NH, BATCH), 256, ATTN_SMEM_BYTES>>>(
        qh, ql, kh, kl, vh, vl, atts);

    // 3) out = att @ w_proj (narrow kernel, fp32 epilogue)
    gemm_narrow<<<dim3(NEMB / 128, MROWS / 128), 256, GEMM_SMEM_BYTES>>>(
        atts, wpT, out, NEMB);
}

// round 13
// speedup vs baseline: 1.0282x; 1.0111x over previous
#include <cuda_runtime.h>
#include <cuda_bf16.h>
#include <cstdint>

// ---------------------------------------------------------------------------
// Problem constants
// ---------------------------------------------------------------------------
#define TSEQ 2048
#define NEMB 768
#define NH   12
#define HD   64
#define BATCH 2
#define MROWS (BATCH * TSEQ)   // 4096
#define QKV_W (3 * NEMB)       // 2304
#define KP    2304             // split-K' = 3 * 768

// ---------------------------------------------------------------------------
// Scratch (__device__ globals; allocation-free rule)
// ---------------------------------------------------------------------------
__device__ __align__(16) __nv_bfloat16 g_xs  [(size_t)MROWS * KP];    // [Ah|Al|Ah] of x
__device__ __align__(16) __nv_bfloat16 g_atts[(size_t)MROWS * KP];    // [Ah|Al|Ah] of att
__device__ __align__(16) __nv_bfloat16 g_wqT [(size_t)QKV_W * KP];    // [N][K'] of w_qkv
__device__ __align__(16) __nv_bfloat16 g_wpT [(size_t)NEMB  * KP];    // [N][K'] of w_proj
// pre-split Q/K/V, head-major [b*NH+h][t][64]
#define QKV_E ((size_t)BATCH * NH * TSEQ * HD)
__device__ __align__(16) __nv_bfloat16 g_qh[QKV_E];
__device__ __align__(16) __nv_bfloat16 g_ql[QKV_E];
__device__ __align__(16) __nv_bfloat16 g_kh[QKV_E];
__device__ __align__(16) __nv_bfloat16 g_kl[QKV_E];
__device__ __align__(16) __nv_bfloat16 g_vh[QKV_E];
__device__ __align__(16) __nv_bfloat16 g_vl[QKV_E];

// ---------------------------------------------------------------------------
// PTX helpers (baseline compute_103-safe: mma.sync / ldmatrix / cp.async)
// ---------------------------------------------------------------------------
__device__ __forceinline__ uint32_t smem_u32(const void* p) {
    uint32_t a;
    asm("{ .reg .u64 t; cvta.to.shared.u64 t, %1; cvt.u32.u64 %0, t; }"
        : "=r"(a) : "l"(p));
    return a;
}
__device__ __forceinline__ void ldsm_x4(uint32_t& r0, uint32_t& r1,
                                        uint32_t& r2, uint32_t& r3, uint32_t addr) {
    asm volatile("ldmatrix.sync.aligned.m8n8.x4.shared.b16 {%0,%1,%2,%3}, [%4];"
                 : "=r"(r0), "=r"(r1), "=r"(r2), "=r"(r3) : "r"(addr));
}
__device__ __forceinline__ void ldsm_x4_t(uint32_t& r0, uint32_t& r1,
                                          uint32_t& r2, uint32_t& r3, uint32_t addr) {
    asm volatile("ldmatrix.sync.aligned.m8n8.x4.trans.shared.b16 {%0,%1,%2,%3}, [%4];"
                 : "=r"(r0), "=r"(r1), "=r"(r2), "=r"(r3) : "r"(addr));
}
__device__ __forceinline__ void mma16816(float* c, const uint32_t* a, const uint32_t* b) {
    asm volatile(
        "mma.sync.aligned.m16n8k16.row.col.f32.bf16.bf16.f32 "
        "{%0,%1,%2,%3}, {%4,%5,%6,%7}, {%8,%9}, {%0,%1,%2,%3};"
        : "+f"(c[0]), "+f"(c[1]), "+f"(c[2]), "+f"(c[3])
        : "r"(a[0]), "r"(a[1]), "r"(a[2]), "r"(a[3]), "r"(b[0]), "r"(b[1]));
}
#define CP_ASYNC16(dst, src) \
    asm volatile("cp.async.cg.shared.global [%0], [%1], 16;" :: "r"(dst), "l"(src) : "memory")
#define CP_COMMIT()  asm volatile("cp.async.commit_group;" ::: "memory")
#define CP_WAIT1()   asm volatile("cp.async.wait_group 1;" ::: "memory")
#define CP_WAIT0()   asm volatile("cp.async.wait_group 0;" ::: "memory")

__device__ __forceinline__ void split2(float a, float b, uint32_t& hi, uint32_t& lo) {
    __nv_bfloat16 ha = __float2bfloat16(a), hb = __float2bfloat16(b);
    hi = (uint32_t)__bfloat16_as_ushort(ha) | ((uint32_t)__bfloat16_as_ushort(hb) << 16);
    __nv_bfloat16 la = __float2bfloat16(a - __bfloat162float(ha));
    __nv_bfloat16 lb = __float2bfloat16(b - __bfloat162float(hb));
    lo = (uint32_t)__bfloat16_as_ushort(la) | ((uint32_t)__bfloat16_as_ushort(lb) << 16);
}

// ---------------------------------------------------------------------------
// bf16 mma.sync GEMM (round-7 proven config). MODE 0: fp32 epilogue to C.
// MODE 1: QKV split epilogue -> g_qh/ql/kh/kl/vh/vl (Q pre-scaled by 0.125).
// ---------------------------------------------------------------------------
#define BKC     64
#define ASTRIDE 72
#define TILE_E  (128 * ASTRIDE)
#define GEMM_SMEM_BYTES (4 * TILE_E * 2)
#define NCHUNK  (KP / BKC)

template<int MODE>
__global__ __launch_bounds__(256) void gemm_bf16_mma(
    const __nv_bfloat16* __restrict__ A,
    const __nv_bfloat16* __restrict__ BT,
    float* __restrict__ C, int N,
    __nv_bfloat16* __restrict__ qh, __nv_bfloat16* __restrict__ ql,
    __nv_bfloat16* __restrict__ kh, __nv_bfloat16* __restrict__ kl,
    __nv_bfloat16* __restrict__ vh, __nv_bfloat16* __restrict__ vl)
{
    extern __shared__ __nv_bfloat16 smb[];
    const uint32_t smem_base = smem_u32(smb);

    const int tid  = threadIdx.x;
    const int wid  = tid >> 5;
    const int lane = tid & 31;
    const int wm   = wid >> 2;
    const int wn   = wid & 3;

    const int m0 = blockIdx.y * 128;
    const int n0 = blockIdx.x * 128;

    const __nv_bfloat16* Ap = A  + (size_t)m0 * KP;
    const __nv_bfloat16* Bp = BT + (size_t)n0 * KP;

    const int ldr = tid >> 3;
    const int ldc = (tid & 7) * 8;

    float acc[4][4][4];
    #pragma unroll
    for (int i = 0; i < 4; i++)
        #pragma unroll
        for (int j = 0; j < 4; j++)
            #pragma unroll
            for (int r = 0; r < 4; r++)
                acc[i][j][r] = 0.f;

    {
        const uint32_t a_s = smem_base;
        const uint32_t b_s = smem_base + TILE_E * 2;
        #pragma unroll
        for (int i = 0; i < 4; i++) {
            const int r = ldr + i * 32;
            CP_ASYNC16(a_s + (uint32_t)(r * ASTRIDE + ldc) * 2,
                       Ap + (size_t)r * KP + ldc);
            CP_ASYNC16(b_s + (uint32_t)(r * ASTRIDE + ldc) * 2,
                       Bp + (size_t)r * KP + ldc);
        }
        CP_COMMIT();
    }

    const int a_row = wm * 64 + (lane & 15);
    const int a_col = (lane >> 4) * 8;
    const int b_row = wn * 32 + (lane & 7);
    const int b_sel = lane >> 3;
    const int b_nadd = (b_sel >> 1) * 8;
    const int b_col  = (b_sel & 1) * 8;

    for (int c = 0; c < NCHUNK; c++) {
        if (c + 1 < NCHUNK) {
            const int nb = (c + 1) & 1;
            const int kc = (c + 1) * BKC;
            const uint32_t a_s = smem_base + (uint32_t)(nb * 2 * TILE_E) * 2;
            const uint32_t b_s = smem_base + (uint32_t)((nb * 2 + 1) * TILE_E) * 2;
            #pragma unroll
            for (int i = 0; i < 4; i++) {
                const int r = ldr + i * 32;
                CP_ASYNC16(a_s + (uint32_t)(r * ASTRIDE + ldc) * 2,
                           Ap + (size_t)r * KP + kc + ldc);
                CP_ASYNC16(b_s + (uint32_t)(r * ASTRIDE + ldc) * 2,
                           Bp + (size_t)r * KP + kc + ldc);
            }
        }
        CP_COMMIT();
        CP_WAIT1();
        __syncthreads();

        const int cb = c & 1;
        const uint32_t a_base = smem_base + (uint32_t)(cb * 2 * TILE_E) * 2;
        const uint32_t b_base = smem_base + (uint32_t)((cb * 2 + 1) * TILE_E) * 2;

        #pragma unroll
        for (int ks = 0; ks < 4; ks++) {
            uint32_t aF[4][4];
            uint32_t bF[4][2];
            #pragma unroll
            for (int mt = 0; mt < 4; mt++)
                ldsm_x4(aF[mt][0], aF[mt][1], aF[mt][2], aF[mt][3],
                        a_base + (uint32_t)((a_row + mt * 16) * ASTRIDE
                                            + ks * 16 + a_col) * 2);
            #pragma unroll
            for (int p = 0; p < 2; p++)
                ldsm_x4(bF[2*p][0], bF[2*p][1], bF[2*p+1][0], bF[2*p+1][1],
                        b_base + (uint32_t)((b_row + p * 16 + b_nadd) * ASTRIDE
                                            + ks * 16 + b_col) * 2);
            #pragma unroll
            for (int mt = 0; mt < 4; mt++)
                #pragma unroll
                for (int nt = 0; nt < 4; nt++)
                    mma16816(acc[mt][nt], aF[mt], bF[nt]);
        }
        __syncthreads();
    }

    if (MODE == 0) {
        #pragma unroll
        for (int mt = 0; mt < 4; mt++) {
            #pragma unroll
            for (int nt = 0; nt < 4; nt++) {
                const int row = m0 + wm * 64 + mt * 16 + (lane >> 2);
                const int col = n0 + wn * 32 + nt * 8 + (lane & 3) * 2;
                float* p0 = C + (size_t)row * N + col;
                float* p1 = C + (size_t)(row + 8) * N + col;
                *reinterpret_cast<float2*>(p0) = make_float2(acc[mt][nt][0], acc[mt][nt][1]);
                *reinterpret_cast<float2*>(p1) = make_float2(acc[mt][nt][2], acc[mt][nt][3]);
            }
        }
    } else {
        #pragma unroll
        for (int mt = 0; mt < 4; mt++) {
            #pragma unroll
            for (int nt = 0; nt < 4; nt++) {
                const int col  = n0 + wn * 32 + nt * 8 + (lane & 3) * 2;
                const int sec  = col / NEMB;            // 0=q,1=k,2=v
                const int rem  = col - sec * NEMB;
                const int head = rem >> 6;
                const int d    = rem & 63;
                __nv_bfloat16* bh = (sec == 0) ? qh : (sec == 1) ? kh : vh;
                __nv_bfloat16* bl = (sec == 0) ? ql : (sec == 1) ? kl : vl;
                const float s = (sec == 0) ? 0.125f : 1.0f;
                #pragma unroll
                for (int hr = 0; hr < 2; hr++) {
                    const int row = m0 + wm * 64 + mt * 16 + (lane >> 2) + hr * 8;
                    const int bb  = row >> 11;
                    const int t   = row & 2047;
                    const size_t off = ((size_t)(bb * NH + head) * TSEQ + t) * HD + d;
                    uint32_t hi, lo;
                    split2(acc[mt][nt][hr * 2] * s, acc[mt][nt][hr * 2 + 1] * s, hi, lo);
                    *reinterpret_cast<uint32_t*>(bh + off) = hi;
                    *reinterpret_cast<uint32_t*>(bl + off) = lo;
                }
            }
        }
    }
}

// ---------------------------------------------------------------------------
// conv_split (vectorized: 4 elements per thread, 16B load, 8B packed stores)
// fp32 [M][768] -> bf16 [M][2304] laid out [hi | lo | hi]
// ---------------------------------------------------------------------------
__global__ __launch_bounds__(256) void conv_split(
    const float* __restrict__ in, __nv_bfloat16* __restrict__ out, int M)
{
    const int idx4 = blockIdx.x * 256 + threadIdx.x;      // float4 index
    if (idx4 >= M * (NEMB / 4)) return;
    const int row  = idx4 / (NEMB / 4);
    const int col4 = idx4 - row * (NEMB / 4);
    float4 v = *reinterpret_cast<const float4*>(in + (size_t)row * NEMB + col4 * 4);
    uint32_t h0, l0, h1, l1;
    split2(v.x, v.y, h0, l0);
    split2(v.z, v.w, h1, l1);
    __nv_bfloat16* o = out + (size_t)row * KP + col4 * 4;
    *reinterpret_cast<uint2*>(o)            = make_uint2(h0, h1);
    *reinterpret_cast<uint2*>(o + NEMB)     = make_uint2(l0, l1);
    *reinterpret_cast<uint2*>(o + 2 * NEMB) = make_uint2(h0, h1);
}

// ---------------------------------------------------------------------------
// conv_wT merged: one launch converts BOTH weights (blockIdx.x range selects).
// fp32 W [768][N] -> bf16 WT [N][2304] with rows [hi ; hi ; lo]
// ---------------------------------------------------------------------------
#define WQ_BLKS (QKV_W / 32)     // 72
#define WP_BLKS (NEMB / 32)      // 24

__global__ __launch_bounds__(256) void conv_wT2(
    const float* __restrict__ Wq, __nv_bfloat16* __restrict__ WqT,
    const float* __restrict__ Wp, __nv_bfloat16* __restrict__ WpT)
{
    __shared__ float t[32][33];
    const int tx = threadIdx.x & 31;
    const int ty = threadIdx.x >> 5;

    int bx = blockIdx.x;
    const float* W;
    __nv_bfloat16* WT;
    int N;
    if (bx < WQ_BLKS) { W = Wq; WT = WqT; N = QKV_W; }
    else              { bx -= WQ_BLKS; W = Wp; WT = WpT; N = NEMB; }

    const int gn = bx * 32;
    const int gk = blockIdx.y * 32;

    #pragma unroll
    for (int i = 0; i < 4; i++)
        t[ty + 8 * i][tx] = W[(size_t)(gk + ty + 8 * i) * N + gn + tx];
    __syncthreads();

    #pragma unroll
    for (int i = 0; i < 4; i++) {
        const int n = gn + ty + 8 * i;
        const float x = t[tx][ty + 8 * i];
        const __nv_bfloat16 hi = __float2bfloat16(x);
        const __nv_bfloat16 lo = __float2bfloat16(x - __bfloat162float(hi));
        __nv_bfloat16* o = WT + (size_t)n * KP + gk + tx;
        o[0]        = hi;
        o[NEMB]     = hi;
        o[2 * NEMB] = lo;
    }
}

// ---------------------------------------------------------------------------
// Tensor-core fused causal attention (round-7 base + merged Phase-A ks loop
// sharing the qf fragment + interior/diagonal path split in the exp stage).
// ---------------------------------------------------------------------------
#define AT_QH_E  0
#define AT_QL_E  9216
#define AT_KV_E  18432                    // + buf*18432
#define AKV_SZ   4608                     // 64*72 elems
#define ATTN_SMEM_BYTES ((18432 + 2 * 18432) * 2)   // 110592

#define KV_LOAD(kt_, buf_) do {                                                   \
    const uint32_t kvs = smb + (uint32_t)(AT_KV_E + (buf_) * 18432) * 2;          \
    _Pragma("unroll")                                                             \
    for (int i_ = 0; i_ < 2; i_++) {                                              \
        const int id_ = tid + i_ * 256;                                           \
        const int r_ = id_ >> 3, c_ = (id_ & 7) * 8;                              \
        const size_t go_ = (bh + (size_t)(kt_) * 64 + r_) * HD + c_;              \
        const uint32_t so_ = (uint32_t)(r_ * 72 + c_) * 2;                        \
        CP_ASYNC16(kvs + so_,                  Kh + go_);                         \
        CP_ASYNC16(kvs + AKV_SZ * 2 + so_,     Kl + go_);                         \
        CP_ASYNC16(kvs + 2 * AKV_SZ * 2 + so_, Vh + go_);                         \
        CP_ASYNC16(kvs + 3 * AKV_SZ * 2 + so_, Vl + go_);                         \
    }                                                                             \
    CP_COMMIT();                                                                  \
} while (0)

__global__ __launch_bounds__(256, 2) void attn_mma(
    const __nv_bfloat16* __restrict__ Qh, const __nv_bfloat16* __restrict__ Ql,
    const __nv_bfloat16* __restrict__ Kh, const __nv_bfloat16* __restrict__ Kl,
    const __nv_bfloat16* __restrict__ Vh, const __nv_bfloat16* __restrict__ Vl,
    __nv_bfloat16* __restrict__ atts)
{
    extern __shared__ __nv_bfloat16 smh[];
    const uint32_t smb = smem_u32(smh);

    const int tid  = threadIdx.x;
    const int wid  = tid >> 5;           // 0..7, owns rows wid*16..+15
    const int lane = tid & 31;

    const int qt = (int)gridDim.x - 1 - (int)blockIdx.x;   // heavy tiles first
    const int h  = blockIdx.y;
    const int b  = blockIdx.z;
    const int q0 = qt * 128;

    const size_t bh = (size_t)(b * NH + h) * TSEQ;

    // ---- issue Q + KV tile 0 loads (one group) ----
    {
        const uint32_t qhs = smb + AT_QH_E * 2;
        const uint32_t qls = smb + AT_QL_E * 2;
        #pragma unroll
        for (int i = 0; i < 4; i++) {
            const int id = tid + i * 256;      // 0..1023
            const int r = id >> 3, c = (id & 7) * 8;
            const size_t go = (bh + q0 + r) * HD + c;
            const uint32_t so = (uint32_t)(r * 72 + c) * 2;
            CP_ASYNC16(qhs + so, Qh + go);
            CP_ASYNC16(qls + so, Ql + go);
        }
        KV_LOAD(0, 0);   // commits the group
    }

    // fragment addressing
    const int lr = lane >> 2;            // 0..7
    const int lc = (lane & 3) * 2;       // 0,2,4,6
    const int a_row = wid * 16 + (lane & 15);
    const int a_col = (lane >> 4) * 8;
    const int b_row = lane & 7;
    const int b_nadd = ((lane >> 4) & 1) * 8;
    const int b_col  = ((lane >> 3) & 1) * 8;
    const int v_roff = (lane & 7) + ((lane >> 3) & 1) * 8;
    const int v_coff = (lane >> 4) * 8;

    const uint32_t qh_b = smb + AT_QH_E * 2;
    const uint32_t ql_b = smb + AT_QL_E * 2;

    float oacc[8][4];
    #pragma unroll
    for (int nt = 0; nt < 8; nt++)
        #pragma unroll
        for (int r = 0; r < 4; r++)
            oacc[nt][r] = 0.f;
    float lsum0 = 0.f, lsum1 = 0.f;

    const int numT = 2 * qt + 2;
    const int wrow0 = q0 + wid * 16;     // warp's first global q-row

    CP_WAIT0();
    __syncthreads();

    for (int kt = 0; kt < numT; kt++) {
        if (kt + 1 < numT) KV_LOAD(kt + 1, (kt + 1) & 1);

        const uint32_t kvb = smb + (uint32_t)(AT_KV_E + (kt & 1) * 18432) * 2;
        const uint32_t kh_b = kvb;
        const uint32_t kl_b = kvb + AKV_SZ * 2;
        const uint32_t vh_b = kvb + 2 * AKV_SZ * 2;
        const uint32_t vl_b = kvb + 3 * AKV_SZ * 2;

        if (kt * 64 <= wrow0 + 15) {     // tile not fully masked for this warp
            // ---- Phase A: S = Q' @ K'^T (merged regions; qf shared) ----
            float sacc[8][4];
            #pragma unroll
            for (int nt = 0; nt < 8; nt++)
                #pragma unroll
                for (int r = 0; r < 4; r++)
                    sacc[nt][r] = 0.f;

            #pragma unroll
            for (int ks = 0; ks < 4; ks++) {
                uint32_t qf[4], qg[4], bF[8][2];
                ldsm_x4(qf[0], qf[1], qf[2], qf[3],
                        qh_b + (uint32_t)(a_row * 72 + ks * 16 + a_col) * 2);
                ldsm_x4(qg[0], qg[1], qg[2], qg[3],
                        ql_b + (uint32_t)(a_row * 72 + ks * 16 + a_col) * 2);
                // Kh region: used by both qf (hi*hi) and qg (lo*hi)
                #pragma unroll
                for (int p = 0; p < 4; p++)
                    ldsm_x4(bF[2*p][0], bF[2*p][1], bF[2*p+1][0], bF[2*p+1][1],
                            kh_b + (uint32_t)((p * 16 + b_nadd + b_row) * 72
                                              + ks * 16 + b_col) * 2);
                #pragma unroll
                for (int nt = 0; nt < 8; nt++) mma16816(sacc[nt], qf, bF[nt]);
                #pragma unroll
                for (int nt = 0; nt < 8; nt++) mma16816(sacc[nt], qg, bF[nt]);
                // Kl region: hi*lo (qf reused — no reload)
                #pragma unroll
                for (int p = 0; p < 4; p++)
                    ldsm_x4(bF[2*p][0], bF[2*p][1], bF[2*p+1][0], bF[2*p+1][1],
                            kl_b + (uint32_t)((p * 16 + b_nadd + b_row) * 72
                                              + ks * 16 + b_col) * 2);
                #pragma unroll
                for (int nt = 0; nt < 8; nt++) mma16816(sacc[nt], qf, bF[nt]);
            }

            // ---- exp + (mask) + register row sums: split interior/diagonal ----
            if (kt * 64 + 63 <= wrow0) {
                // interior tile: no masking needed for any row of this warp
                #pragma unroll
                for (int nt = 0; nt < 8; nt++) {
                    #pragma unroll
                    for (int r = 0; r < 4; r++) {
                        const float e = __expf(sacc[nt][r]);
                        sacc[nt][r] = e;
                        if (r < 2) lsum0 += e; else lsum1 += e;
                    }
                }
            } else {
                #pragma unroll
                for (int nt = 0; nt < 8; nt++) {
                    #pragma unroll
                    for (int r = 0; r < 4; r++) {
                        float e = __expf(sacc[nt][r]);
                        const int colg = kt * 64 + nt * 8 + lc + (r & 1);
                        const int rowg = wrow0 + lr + (r >> 1) * 8;
                        if (colg > rowg) e = 0.f;
                        sacc[nt][r] = e;
                        if (r < 2) lsum0 += e; else lsum1 += e;
                    }
                }
            }

            // ---- pack P A-fragments directly from S C-fragments ----
            uint32_t phF[4][4], plF[4][4];
            #pragma unroll
            for (int ks = 0; ks < 4; ks++) {
                split2(sacc[2*ks][0],   sacc[2*ks][1],   phF[ks][0], plF[ks][0]);
                split2(sacc[2*ks][2],   sacc[2*ks][3],   phF[ks][1], plF[ks][1]);
                split2(sacc[2*ks+1][0], sacc[2*ks+1][1], phF[ks][2], plF[ks][2]);
                split2(sacc[2*ks+1][2], sacc[2*ks+1][3], phF[ks][3], plF[ks][3]);
            }

            // ---- Phase B: O += Ph@Vh + Pl@Vh + Ph@Vl ----
            #pragma unroll
            for (int ks = 0; ks < 4; ks++) {
                uint32_t bF[8][2];
                #pragma unroll
                for (int p = 0; p < 4; p++)
                    ldsm_x4_t(bF[2*p][0], bF[2*p][1], bF[2*p+1][0], bF[2*p+1][1],
                              vh_b + (uint32_t)((ks * 16 + v_roff) * 72
                                                + p * 16 + v_coff) * 2);
                #pragma unroll
                for (int nt = 0; nt < 8; nt++) mma16816(oacc[nt], phF[ks], bF[nt]);
                #pragma unroll
                for (int nt = 0; nt < 8; nt++) mma16816(oacc[nt], plF[ks], bF[nt]);
            }
            #pragma unroll
            for (int ks = 0; ks < 4; ks++) {
                uint32_t bF[8][2];
                #pragma unroll
                for (int p = 0; p < 4; p++)
                    ldsm_x4_t(bF[2*p][0], bF[2*p][1], bF[2*p+1][0], bF[2*p+1][1],
                              vl_b + (uint32_t)((ks * 16 + v_roff) * 72
                                                + p * 16 + v_coff) * 2);
                #pragma unroll
                for (int nt = 0; nt < 8; nt++) mma16816(oacc[nt], phF[ks], bF[nt]);
            }
        }

        if (kt + 1 < numT) {
            CP_WAIT0();
            __syncthreads();   // tile kt+1 resident & visible; all warps done with kt
        }
    }

    // ---- final row-sum reduce (within 4-lane quad) ----
    lsum0 += __shfl_xor_sync(0xFFFFFFFFu, lsum0, 1);
    lsum0 += __shfl_xor_sync(0xFFFFFFFFu, lsum0, 2);
    lsum1 += __shfl_xor_sync(0xFFFFFFFFu, lsum1, 1);
    lsum1 += __shfl_xor_sync(0xFFFFFFFFu, lsum1, 2);
    const float inv0 = 1.f / lsum0;
    const float inv1 = 1.f / lsum1;

    // ---- normalize + split-store into atts ([Ah|Al|Ah]) ----
    const size_t row0 = (size_t)(b * TSEQ + wrow0 + lr);
    #pragma unroll
    for (int nt = 0; nt < 8; nt++) {
        const int col = h * HD + nt * 8 + lc;
        uint32_t hi, lo;
        split2(oacc[nt][0] * inv0, oacc[nt][1] * inv0, hi, lo);
        __nv_bfloat16* op = atts + row0 * KP + col;
        *reinterpret_cast<uint32_t*>(op)            = hi;
        *reinterpret_cast<uint32_t*>(op + NEMB)     = lo;
        *reinterpret_cast<uint32_t*>(op + 2 * NEMB) = hi;
        split2(oacc[nt][2] * inv1, oacc[nt][3] * inv1, hi, lo);
        op = atts + (row0 + 8) * KP + col;
        *reinterpret_cast<uint32_t*>(op)            = hi;
        *reinterpret_cast<uint32_t*>(op + NEMB)     = lo;
        *reinterpret_cast<uint32_t*>(op + 2 * NEMB) = hi;
    }
}

// ---------------------------------------------------------------------------
extern "C" void kernel_launch(void* const* d_in, const int* in_sizes, int n_in,
                              void* d_out, int out_size)
{
    const float* x      = (const float*)d_in[0];   // [2,2048,768]
    const float* w_qkv  = (const float*)d_in[1];   // [768,2304]
    const float* w_proj = (const float*)d_in[2];   // [768,768]
    float* out = (float*)d_out;                    // [2,2048,768]

    __nv_bfloat16 *xs, *atts, *wqT, *wpT, *qh, *ql, *kh, *kl, *vh, *vl;
    cudaGetSymbolAddress((void**)&xs,   g_xs);
    cudaGetSymbolAddress((void**)&atts, g_atts);
    cudaGetSymbolAddress((void**)&wqT,  g_wqT);
    cudaGetSymbolAddress((void**)&wpT,  g_wpT);
    cudaGetSymbolAddress((void**)&qh,   g_qh);
    cudaGetSymbolAddress((void**)&ql,   g_ql);
    cudaGetSymbolAddress((void**)&kh,   g_kh);
    cudaGetSymbolAddress((void**)&kl,   g_kl);
    cudaGetSymbolAddress((void**)&vh,   g_vh);
    cudaGetSymbolAddress((void**)&vl,   g_vl);

    cudaFuncSetAttribute(gemm_bf16_mma<0>,
                         cudaFuncAttributeMaxDynamicSharedMemorySize, GEMM_SMEM_BYTES);
    cudaFuncSetAttribute(gemm_bf16_mma<1>,
                         cudaFuncAttributeMaxDynamicSharedMemorySize, GEMM_SMEM_BYTES);
    cudaFuncSetAttribute(attn_mma,
                         cudaFuncAttributeMaxDynamicSharedMemorySize, ATTN_SMEM_BYTES);

    // 0) split/convert inputs (2 launches instead of 3)
    conv_split<<<(MROWS * (NEMB / 4) + 255) / 256, 256>>>(x, xs, MROWS);
    conv_wT2<<<dim3(WQ_BLKS + WP_BLKS, NEMB / 32), 256>>>(w_qkv, wqT, w_proj, wpT);

    // 1) qkv GEMM with split epilogue -> pre-split Q/K/V buffers
    gemm_bf16_mma<1><<<dim3(QKV_W / 128, MROWS / 128), 256, GEMM_SMEM_BYTES>>>(
        xs, wqT, nullptr, QKV_W, qh, ql, kh, kl, vh, vl);

    // 2) fused causal attention -> atts (pre-split for proj)
    attn_mma<<<dim3(TSEQ / 128, NH, BATCH), 256, ATTN_SMEM_BYTES>>>(
        qh, ql, kh, kl, vh, vl, atts);

    // 3) out = att @ w_proj
    gemm_bf16_mma<0><<<dim3(NEMB / 128, MROWS / 128), 256, GEMM_SMEM_BYTES>>>(
        atts, wpT, out, NEMB, nullptr, nullptr, nullptr, nullptr, nullptr, nullptr);
}